// round 2
// baseline (speedup 1.0000x reference)
#include <cuda_runtime.h>
#include <math.h>

#define B_   4
#define L_   4096
#define E_   1024
#define H_   16
#define HD_  64
#define M_   (B_*L_)    // 16384 rows
#define BH_  (B_*H_)    // 64 heads
#define EPS_ 1e-4f

// ---------------- scratch (no allocations allowed) ----------------
__device__ float g_q[M_*E_];
__device__ float g_k[M_*E_];
__device__ float g_v[M_*E_];
__device__ float g_attn[M_*E_];
__device__ float g_kv[BH_*128*HD_];   // per head: [2hd=128][hd=64]
__device__ float g_ksum[BH_*128];

// ---------------- GEMM: C[m,n] = sum_k A[m,k]*W[n,k] + bias[n] (opt ReLU) ----
// A: (Mdim,Kdim) row-major; W: (Ndim,Kdim) row-major (torch Linear weight)
template<int RELU>
__global__ __launch_bounds__(256, 2)
void gemm_kernel(const float* __restrict__ A, const float* __restrict__ W,
                 const float* __restrict__ bias, float* __restrict__ C,
                 int Mdim, int Ndim, int Kdim)
{
    const int BM = 128, BN = 128, BK = 16;
    __shared__ float As[BK][BM + 4];
    __shared__ float Bs[BK][BN + 4];

    const int bm = blockIdx.y * BM;
    const int bn = blockIdx.x * BN;
    const int t  = threadIdx.x;
    const int tx = t & 15;      // 0..15 -> n microtile
    const int ty = t >> 4;      // 0..15 -> m microtile

    float acc[8][8];
    #pragma unroll
    for (int i = 0; i < 8; i++)
        #pragma unroll
        for (int j = 0; j < 8; j++) acc[i][j] = 0.f;

    const int lrow = t >> 2;        // 0..63
    const int lk4  = (t & 3) * 4;   // 0,4,8,12

    for (int k0 = 0; k0 < Kdim; k0 += BK) {
        #pragma unroll
        for (int r = 0; r < 2; r++) {
            int row = lrow + r * 64;
            float4 va = *(const float4*)&A[(size_t)(bm + row) * Kdim + k0 + lk4];
            As[lk4+0][row] = va.x; As[lk4+1][row] = va.y;
            As[lk4+2][row] = va.z; As[lk4+3][row] = va.w;
            float4 vb = *(const float4*)&W[(size_t)(bn + row) * Kdim + k0 + lk4];
            Bs[lk4+0][row] = vb.x; Bs[lk4+1][row] = vb.y;
            Bs[lk4+2][row] = vb.z; Bs[lk4+3][row] = vb.w;
        }
        __syncthreads();
        #pragma unroll
        for (int kk = 0; kk < BK; kk++) {
            float a[8], bb[8];
            #pragma unroll
            for (int i = 0; i < 8; i++) a[i]  = As[kk][ty*8 + i];
            #pragma unroll
            for (int j = 0; j < 8; j++) bb[j] = Bs[kk][tx*8 + j];
            #pragma unroll
            for (int i = 0; i < 8; i++)
                #pragma unroll
                for (int j = 0; j < 8; j++)
                    acc[i][j] += a[i] * bb[j];
        }
        __syncthreads();
    }

    #pragma unroll
    for (int i = 0; i < 8; i++) {
        int row = bm + ty*8 + i;
        #pragma unroll
        for (int j = 0; j < 8; j++) {
            int col = bn + tx*8 + j;
            float v = acc[i][j] + bias[col];
            if (RELU) v = fmaxf(v, 0.f);
            C[(size_t)row * Ndim + col] = v;
        }
    }
}

// ---------------- kv + ksum: one block per head (deterministic) -------------
// kv[d][m] = sum_l w(l,d)*k[l, d%64] * v[l,m],   w = sin for d<64 else cos
__global__ __launch_bounds__(256)
void kv_kernel(const float* __restrict__ k, const float* __restrict__ v)
{
    const int head = blockIdx.x;            // 0..63
    const int b = head / H_, h = head % H_;
    __shared__ float ks[32][128];           // expanded k_ chunk
    __shared__ float vs[32][68];            // padded

    const int t  = threadIdx.x;
    const int tx = t & 15;                  // m microtile (4 cols)
    const int ty = t >> 4;                  // d microtile (8 rows)

    float acc[8][4];
    #pragma unroll
    for (int i = 0; i < 8; i++)
        #pragma unroll
        for (int j = 0; j < 4; j++) acc[i][j] = 0.f;
    float ksum_acc = 0.f;

    for (int l0 = 0; l0 < L_; l0 += 32) {
        #pragma unroll
        for (int r = 0; r < 2; r++) {
            int i   = t + r * 256;          // 0..511 float4 slots
            int row = i >> 4;               // 0..31
            int c4  = (i & 15) * 4;         // 0..60
            int l   = l0 + row;
            float ang = (float)M_PI * 0.5f * (float)(l + 1) / (float)L_;
            float s, c;
            sincosf(ang, &s, &c);
            size_t base = ((size_t)(b * L_ + l)) * E_ + h * HD_ + c4;
            float4 kk4 = *(const float4*)&k[base];
            ks[row][c4+0]    = s * kk4.x; ks[row][c4+1]    = s * kk4.y;
            ks[row][c4+2]    = s * kk4.z; ks[row][c4+3]    = s * kk4.w;
            ks[row][64+c4+0] = c * kk4.x; ks[row][64+c4+1] = c * kk4.y;
            ks[row][64+c4+2] = c * kk4.z; ks[row][64+c4+3] = c * kk4.w;
            float4 vv4 = *(const float4*)&v[base];
            vs[row][c4+0] = vv4.x; vs[row][c4+1] = vv4.y;
            vs[row][c4+2] = vv4.z; vs[row][c4+3] = vv4.w;
        }
        __syncthreads();

        if (t < 128) {
            #pragma unroll
            for (int l = 0; l < 32; l++) ksum_acc += ks[l][t];
        }
        #pragma unroll 4
        for (int l = 0; l < 32; l++) {
            float a[8], bb[4];
            #pragma unroll
            for (int i = 0; i < 8; i++) a[i]  = ks[l][ty*8 + i];
            #pragma unroll
            for (int j = 0; j < 4; j++) bb[j] = vs[l][tx*4 + j];
            #pragma unroll
            for (int i = 0; i < 8; i++)
                #pragma unroll
                for (int j = 0; j < 4; j++)
                    acc[i][j] += a[i] * bb[j];
        }
        __syncthreads();
    }

    #pragma unroll
    for (int i = 0; i < 8; i++)
        #pragma unroll
        for (int j = 0; j < 4; j++)
            g_kv[((size_t)head * 128 + ty*8 + i) * HD_ + tx*4 + j] = acc[i][j];
    if (t < 128) g_ksum[head * 128 + t] = ksum_acc;
}

// ---------------- attn: out[l,m] = z(l) * sum_d q_[l,d]*kv[d,m] -------------
__global__ __launch_bounds__(256)
void attn_kernel(const float* __restrict__ q)
{
    const int ltile = blockIdx.x;           // 0..31 (128 l each)
    const int head  = blockIdx.y;           // 0..63
    const int b = head / H_, h = head % H_;

    __shared__ float kvs[128][64];
    __shared__ float ksums[128];
    __shared__ float qrow[8][128];

    const int t = threadIdx.x;
    const int w = t >> 5, lane = t & 31;

    const float* kvg = &g_kv[(size_t)head * 128 * HD_];
    #pragma unroll
    for (int r = 0; r < 8; r++) {
        int i = t + r * 256;                // 0..2047 float4 slots
        ((float4*)kvs)[i] = ((const float4*)kvg)[i];
    }
    if (t < 128) ksums[t] = g_ksum[head * 128 + t];
    __syncthreads();

    for (int it = 0; it < 16; it++) {
        int l = ltile * 128 + it * 8 + w;
        size_t base = ((size_t)(b * L_ + l)) * E_ + h * HD_;
        float ang = (float)M_PI * 0.5f * (float)(l + 1) / (float)L_;
        float s, c;
        sincosf(ang, &s, &c);
        float q0 = q[base + lane];
        float q1 = q[base + 32 + lane];
        qrow[w][lane]      = s * q0;
        qrow[w][32 + lane] = s * q1;
        qrow[w][64 + lane] = c * q0;
        qrow[w][96 + lane] = c * q1;
        __syncwarp();

        // z = 1/max(q_ . ksum, eps)
        float zp = qrow[w][lane]      * ksums[lane]
                 + qrow[w][32 + lane] * ksums[32 + lane]
                 + qrow[w][64 + lane] * ksums[64 + lane]
                 + qrow[w][96 + lane] * ksums[96 + lane];
        #pragma unroll
        for (int o = 16; o > 0; o >>= 1) zp += __shfl_xor_sync(0xffffffffu, zp, o);
        float z = 1.f / fmaxf(zp, EPS_);

        float2 accum = make_float2(0.f, 0.f);
        #pragma unroll 8
        for (int d = 0; d < 128; d++) {
            float qd = qrow[w][d];
            float2 kv2 = *(const float2*)&kvs[d][lane * 2];
            accum.x += qd * kv2.x;
            accum.y += qd * kv2.y;
        }
        *(float2*)&g_attn[base + lane * 2] = make_float2(accum.x * z, accum.y * z);
        __syncwarp();
    }
}

// ---------------- launcher --------------------------------------------------
extern "C" void kernel_launch(void* const* d_in, const int* in_sizes, int n_in,
                              void* d_out, int out_size)
{
    const float* x  = (const float*)d_in[0];
    const float* Wq = (const float*)d_in[1];
    const float* bq = (const float*)d_in[2];
    const float* Wk = (const float*)d_in[3];
    const float* bk = (const float*)d_in[4];
    const float* Wv = (const float*)d_in[5];
    const float* bv = (const float*)d_in[6];
    const float* Wo = (const float*)d_in[7];
    const float* bo = (const float*)d_in[8];
    float* out = (float*)d_out;

    float *q, *k, *v, *attn;
    cudaGetSymbolAddress((void**)&q,    g_q);
    cudaGetSymbolAddress((void**)&k,    g_k);
    cudaGetSymbolAddress((void**)&v,    g_v);
    cudaGetSymbolAddress((void**)&attn, g_attn);

    dim3 gg(E_ / 128, M_ / 128);   // (8, 128)
    gemm_kernel<1><<<gg, 256>>>(x,    Wq, bq, q,   M_, E_, E_);
    gemm_kernel<1><<<gg, 256>>>(x,    Wk, bk, k,   M_, E_, E_);
    gemm_kernel<0><<<gg, 256>>>(x,    Wv, bv, v,   M_, E_, E_);
    kv_kernel<<<BH_, 256>>>(k, v);
    attn_kernel<<<dim3(32, 64), 256>>>(q);
    gemm_kernel<0><<<gg, 256>>>(attn, Wo, bo, out, M_, E_, E_);
}

// round 4
// speedup vs baseline: 2.2720x; 2.2720x over previous
#include <cuda_runtime.h>
#include <cuda_bf16.h>
#include <math.h>
#include <stdint.h>

#define B_   4
#define L_   4096
#define E_   1024
#define H_   16
#define HD_  64
#define M_   (B_*L_)    // 16384 rows
#define BH_  (B_*H_)    // 64 heads
#define EPS_ 1e-4f
#define KTOT 3072       // 3 * 1024 split segments
#define NCHUNK 8        // kv l-chunks

// ---------------- scratch (no allocations allowed) ----------------
__device__ __nv_bfloat16 g_x2[(size_t)M_*KTOT];     // [Ah|Ah|Al]
__device__ __nv_bfloat16 g_attn2[(size_t)M_*KTOT];  // [Ah|Ah|Al]
__device__ __nv_bfloat16 g_w2[4][(size_t)E_*KTOT];  // [Wh|Wl|Wh]
__device__ float g_q[(size_t)M_*E_];
__device__ float g_k[(size_t)M_*E_];
__device__ float g_v[(size_t)M_*E_];
__device__ float g_kvp[NCHUNK*BH_*128*HD_];
__device__ float g_ksump[NCHUNK*BH_*128];
__device__ float g_kv[BH_*128*HD_];
__device__ float g_ksum[BH_*128];

// ================= PTX helpers (sm_80-generic only!) =================
__device__ __forceinline__ uint32_t smem_u32(const void* p) {
    uint32_t a;
    asm("{ .reg .u64 t; cvta.to.shared.u64 t, %1; cvt.u32.u64 %0, t; }" : "=r"(a) : "l"(p));
    return a;
}
__device__ __forceinline__ void cp_async16(uint32_t saddr, const void* gaddr) {
    asm volatile("cp.async.cg.shared.global [%0], [%1], 16;" :: "r"(saddr), "l"(gaddr) : "memory");
}
__device__ __forceinline__ void cp_commit() {
    asm volatile("cp.async.commit_group;" ::: "memory");
}
template<int N> __device__ __forceinline__ void cp_wait_group() {
    asm volatile("cp.async.wait_group %0;" :: "n"(N) : "memory");
}
__device__ __forceinline__ void ldmatrix_x4(uint32_t* r, uint32_t addr) {
    asm volatile("ldmatrix.sync.aligned.m8n8.x4.shared.b16 {%0,%1,%2,%3}, [%4];"
        : "=r"(r[0]), "=r"(r[1]), "=r"(r[2]), "=r"(r[3]) : "r"(addr));
}
__device__ __forceinline__ void mma_bf16(float* c, const uint32_t* a, uint32_t b0, uint32_t b1) {
    asm volatile("mma.sync.aligned.m16n8k16.row.col.f32.bf16.bf16.f32 "
        "{%0,%1,%2,%3}, {%4,%5,%6,%7}, {%8,%9}, {%0,%1,%2,%3};"
        : "+f"(c[0]), "+f"(c[1]), "+f"(c[2]), "+f"(c[3])
        : "r"(a[0]), "r"(a[1]), "r"(a[2]), "r"(a[3]), "r"(b0), "r"(b1));
}
__device__ __forceinline__ uint32_t swz(uint32_t off) { return off ^ ((off >> 3) & 0x70); }

// ================= split conversion kernels =================
// AMODE=1: [hi|hi|lo] (activation side).  AMODE=0: [hi|lo|hi] (weight side).
template<int AMODE>
__global__ void split_kernel(const float* __restrict__ in, __nv_bfloat16* __restrict__ out, int rows)
{
    int idx = blockIdx.x * blockDim.x + threadIdx.x;          // one float4 per thread
    int total = rows * (E_ / 4);
    if (idx >= total) return;
    int row = idx >> 8;
    int c4  = (idx & 255) * 4;
    float4 v = *(const float4*)&in[(size_t)row * E_ + c4];
    __nv_bfloat16 hx = __float2bfloat16(v.x), hy = __float2bfloat16(v.y);
    __nv_bfloat16 hz = __float2bfloat16(v.z), hw = __float2bfloat16(v.w);
    __nv_bfloat16 lx = __float2bfloat16(v.x - __bfloat162float(hx));
    __nv_bfloat16 ly = __float2bfloat16(v.y - __bfloat162float(hy));
    __nv_bfloat16 lz = __float2bfloat16(v.z - __bfloat162float(hz));
    __nv_bfloat16 lw = __float2bfloat16(v.w - __bfloat162float(hw));
    union { __nv_bfloat16 b[4]; uint2 u; } Hh, Ll;
    Hh.b[0]=hx; Hh.b[1]=hy; Hh.b[2]=hz; Hh.b[3]=hw;
    Ll.b[0]=lx; Ll.b[1]=ly; Ll.b[2]=lz; Ll.b[3]=lw;
    __nv_bfloat16* ob = out + (size_t)row * KTOT + c4;
    *(uint2*)(ob)          = Hh.u;
    *(uint2*)(ob + 1024)   = AMODE ? Hh.u : Ll.u;
    *(uint2*)(ob + 2048)   = AMODE ? Ll.u : Hh.u;
}

// ================= HMMA GEMM =================
// C[M,1024] = A2[M,3072] x W2[1024,3072]^T (+bias, opt ReLU), bf16 in fp32 acc
// Tile 128x128x64, 8 warps, warp tile 64x32, mma.sync m16n8k16.
#define GBM 128
#define GBN 128
#define SLAB 64                 // bf16 K per slab = 128 bytes per row
#define NSLAB (KTOT/SLAB)       // 48
#define NSTG 3
#define AB_BYTES (GBM*128)      // 16384 (A tile == B tile size)
#define STG_BYTES (2*AB_BYTES)  // 32768
#define GEMM_DSMEM (NSTG*STG_BYTES + 1024)

__device__ __forceinline__ void gemm_issue_loads(
    const __nv_bfloat16* ga, const __nv_bfloat16* gw,
    uint32_t base, int slab, int buf, int t)
{
    int k0 = slab * SLAB;
    uint32_t stA = base + buf * STG_BYTES;
    uint32_t stW = stA + AB_BYTES;
    const __nv_bfloat16* gak = ga + k0;
    const __nv_bfloat16* gwk = gw + k0;
    #pragma unroll
    for (int j = 0; j < 4; j++) {
        int i = t + j * 256;            // 0..1023
        int row = i >> 3, c = i & 7;
        cp_async16(stA + swz(row * 128 + c * 16), gak + (size_t)row * KTOT + c * 8);
    }
    #pragma unroll
    for (int j = 0; j < 4; j++) {
        int i = t + j * 256;
        int row = i >> 3, c = i & 7;
        cp_async16(stW + swz(row * 128 + c * 16), gwk + (size_t)row * KTOT + c * 8);
    }
    cp_commit();
}

template<int RELU>
__global__ __launch_bounds__(256, 2)
void gemm_mma(const __nv_bfloat16* __restrict__ A2, const __nv_bfloat16* __restrict__ W2,
              const float* __restrict__ bias, float* __restrict__ C)
{
    extern __shared__ char dsm[];
    const int t = threadIdx.x;
    const int wid = t >> 5, lane = t & 31;
    const int wm = wid >> 2;            // 0..1  (64 rows each)
    const int wn = wid & 3;             // 0..3  (32 cols each)
    const int bm = blockIdx.y * GBM;
    const int bn = blockIdx.x * GBN;

    uint32_t base = (smem_u32(dsm) + 1023u) & ~1023u;

    const __nv_bfloat16* ga = A2 + (size_t)bm * KTOT;
    const __nv_bfloat16* gw = W2 + (size_t)bn * KTOT;

    float acc[4][4][4];
    #pragma unroll
    for (int mi = 0; mi < 4; mi++)
        #pragma unroll
        for (int ni = 0; ni < 4; ni++)
            #pragma unroll
            for (int r = 0; r < 4; r++) acc[mi][ni][r] = 0.f;

    // prologue: stages 0..NSTG-2
    #pragma unroll
    for (int s = 0; s < NSTG - 1; s++) gemm_issue_loads(ga, gw, base, s, s, t);

    const int lrow = lane & 15;
    const int lhalf = (lane >> 4) * 16;   // byte offset within 32B k16 chunk

    for (int i = 0; i < NSLAB; i++) {
        cp_wait_group<NSTG - 2>();
        __syncthreads();
        if (i + NSTG - 1 < NSLAB)
            gemm_issue_loads(ga, gw, base, i + NSTG - 1, (i + NSTG - 1) % NSTG, t);
        else
            cp_commit();

        uint32_t sA = base + (i % NSTG) * STG_BYTES;
        uint32_t sB = sA + AB_BYTES;

        #pragma unroll
        for (int kk = 0; kk < 4; kk++) {
            uint32_t a[4][4], b[2][4];
            #pragma unroll
            for (int mi = 0; mi < 4; mi++) {
                uint32_t off = (uint32_t)(wm * 64 + mi * 16 + lrow) * 128 + kk * 32 + lhalf;
                ldmatrix_x4(a[mi], sA + swz(off));
            }
            #pragma unroll
            for (int nb = 0; nb < 2; nb++) {
                uint32_t off = (uint32_t)(wn * 32 + nb * 16 + lrow) * 128 + kk * 32 + lhalf;
                ldmatrix_x4(b[nb], sB + swz(off));
            }
            #pragma unroll
            for (int mi = 0; mi < 4; mi++)
                #pragma unroll
                for (int ni = 0; ni < 4; ni++) {
                    int nb = ni >> 1, hi = ni & 1;
                    mma_bf16(acc[mi][ni], a[mi], b[nb][hi], b[nb][hi + 2]);
                }
        }
        __syncthreads();
    }

    // epilogue: bias (+ReLU) and store
    const int qrow = lane >> 2;          // 0..7
    const int qcol = (lane & 3) * 2;
    #pragma unroll
    for (int mi = 0; mi < 4; mi++) {
        int row0 = bm + wm * 64 + mi * 16 + qrow;
        #pragma unroll
        for (int ni = 0; ni < 4; ni++) {
            int col = bn + wn * 32 + ni * 8 + qcol;
            float2 bb = *(const float2*)&bias[col];
            float v0 = acc[mi][ni][0] + bb.x;
            float v1 = acc[mi][ni][1] + bb.y;
            float v2 = acc[mi][ni][2] + bb.x;
            float v3 = acc[mi][ni][3] + bb.y;
            if (RELU) {
                v0 = fmaxf(v0, 0.f); v1 = fmaxf(v1, 0.f);
                v2 = fmaxf(v2, 0.f); v3 = fmaxf(v3, 0.f);
            }
            *(float2*)&C[(size_t)row0 * E_ + col]       = make_float2(v0, v1);
            *(float2*)&C[(size_t)(row0 + 8) * E_ + col] = make_float2(v2, v3);
        }
    }
}

// ================= kv partial + reduce =================
__global__ __launch_bounds__(256)
void kv_partial(const float* __restrict__ k, const float* __restrict__ v)
{
    const int head = blockIdx.x;            // 0..63
    const int chunk = blockIdx.y;           // 0..7
    const int b = head / H_, h = head % H_;
    __shared__ float ks[32][128];
    __shared__ float vs[32][68];

    const int t  = threadIdx.x;
    const int tx = t & 15;
    const int ty = t >> 4;

    float acc[8][4];
    #pragma unroll
    for (int i = 0; i < 8; i++)
        #pragma unroll
        for (int j = 0; j < 4; j++) acc[i][j] = 0.f;
    float ksum_acc = 0.f;

    const int l_begin = chunk * (L_ / NCHUNK);
    const int l_end   = l_begin + (L_ / NCHUNK);

    for (int l0 = l_begin; l0 < l_end; l0 += 32) {
        #pragma unroll
        for (int r = 0; r < 2; r++) {
            int i   = t + r * 256;
            int row = i >> 4;
            int c4  = (i & 15) * 4;
            int l   = l0 + row;
            float ang = (float)M_PI * 0.5f * (float)(l + 1) / (float)L_;
            float s, c;
            sincosf(ang, &s, &c);
            size_t bse = ((size_t)(b * L_ + l)) * E_ + h * HD_ + c4;
            float4 kk4 = *(const float4*)&k[bse];
            ks[row][c4+0]    = s * kk4.x; ks[row][c4+1]    = s * kk4.y;
            ks[row][c4+2]    = s * kk4.z; ks[row][c4+3]    = s * kk4.w;
            ks[row][64+c4+0] = c * kk4.x; ks[row][64+c4+1] = c * kk4.y;
            ks[row][64+c4+2] = c * kk4.z; ks[row][64+c4+3] = c * kk4.w;
            float4 vv4 = *(const float4*)&v[bse];
            vs[row][c4+0] = vv4.x; vs[row][c4+1] = vv4.y;
            vs[row][c4+2] = vv4.z; vs[row][c4+3] = vv4.w;
        }
        __syncthreads();

        if (t < 128) {
            #pragma unroll
            for (int l = 0; l < 32; l++) ksum_acc += ks[l][t];
        }
        #pragma unroll 4
        for (int l = 0; l < 32; l++) {
            float a[8], bb[4];
            #pragma unroll
            for (int i = 0; i < 8; i++) a[i]  = ks[l][ty*8 + i];
            #pragma unroll
            for (int j = 0; j < 4; j++) bb[j] = vs[l][tx*4 + j];
            #pragma unroll
            for (int i = 0; i < 8; i++)
                #pragma unroll
                for (int j = 0; j < 4; j++)
                    acc[i][j] += a[i] * bb[j];
        }
        __syncthreads();
    }

    float* kvout = &g_kvp[((size_t)(chunk * BH_ + head)) * 128 * HD_];
    #pragma unroll
    for (int i = 0; i < 8; i++)
        #pragma unroll
        for (int j = 0; j < 4; j++)
            kvout[(ty*8 + i) * HD_ + tx*4 + j] = acc[i][j];
    if (t < 128) g_ksump[(chunk * BH_ + head) * 128 + t] = ksum_acc;
}

__global__ __launch_bounds__(256)
void kv_reduce()
{
    int head = blockIdx.x;
    int t = threadIdx.x;
    for (int e = t; e < 128 * HD_; e += 256) {
        float s = 0.f;
        #pragma unroll
        for (int c = 0; c < NCHUNK; c++)
            s += g_kvp[((size_t)(c * BH_ + head)) * 128 * HD_ + e];
        g_kv[(size_t)head * 128 * HD_ + e] = s;
    }
    if (t < 128) {
        float s = 0.f;
        #pragma unroll
        for (int c = 0; c < NCHUNK; c++)
            s += g_ksump[(c * BH_ + head) * 128 + t];
        g_ksum[head * 128 + t] = s;
    }
}

// ================= attn: out = z * q_ . kv, written directly as split bf16 ===
__global__ __launch_bounds__(256)
void attn_kernel(const float* __restrict__ q)
{
    const int ltile = blockIdx.x;           // 0..31
    const int head  = blockIdx.y;           // 0..63
    const int b = head / H_, h = head % H_;

    __shared__ float kvs[128][64];
    __shared__ float ksums[128];
    __shared__ float qrow[8][128];

    const int t = threadIdx.x;
    const int w = t >> 5, lane = t & 31;

    const float* kvg = &g_kv[(size_t)head * 128 * HD_];
    #pragma unroll
    for (int r = 0; r < 8; r++) {
        int i = t + r * 256;
        ((float4*)kvs)[i] = ((const float4*)kvg)[i];
    }
    if (t < 128) ksums[t] = g_ksum[head * 128 + t];
    __syncthreads();

    for (int it = 0; it < 16; it++) {
        int l = ltile * 128 + it * 8 + w;
        size_t qbase = ((size_t)(b * L_ + l)) * E_ + h * HD_;
        float ang = (float)M_PI * 0.5f * (float)(l + 1) / (float)L_;
        float s, c;
        sincosf(ang, &s, &c);
        float q0 = q[qbase + lane];
        float q1 = q[qbase + 32 + lane];
        qrow[w][lane]      = s * q0;
        qrow[w][32 + lane] = s * q1;
        qrow[w][64 + lane] = c * q0;
        qrow[w][96 + lane] = c * q1;
        __syncwarp();

        float zp = qrow[w][lane]      * ksums[lane]
                 + qrow[w][32 + lane] * ksums[32 + lane]
                 + qrow[w][64 + lane] * ksums[64 + lane]
                 + qrow[w][96 + lane] * ksums[96 + lane];
        #pragma unroll
        for (int o = 16; o > 0; o >>= 1) zp += __shfl_xor_sync(0xffffffffu, zp, o);
        float z = 1.f / fmaxf(zp, EPS_);

        float2 accum = make_float2(0.f, 0.f);
        #pragma unroll 8
        for (int d = 0; d < 128; d++) {
            float qd = qrow[w][d];
            float2 kv2 = *(const float2*)&kvs[d][lane * 2];
            accum.x += qd * kv2.x;
            accum.y += qd * kv2.y;
        }
        float ax = accum.x * z, ay = accum.y * z;
        __nv_bfloat16 hx = __float2bfloat16(ax), hy = __float2bfloat16(ay);
        __nv_bfloat16 lx = __float2bfloat16(ax - __bfloat162float(hx));
        __nv_bfloat16 ly = __float2bfloat16(ay - __bfloat162float(hy));
        union { __nv_bfloat16 b2[2]; uint32_t u; } Hh, Ll;
        Hh.b2[0] = hx; Hh.b2[1] = hy;
        Ll.b2[0] = lx; Ll.b2[1] = ly;
        __nv_bfloat16* ob = g_attn2 + ((size_t)(b * L_ + l)) * KTOT + h * HD_ + lane * 2;
        *(uint32_t*)(ob)        = Hh.u;
        *(uint32_t*)(ob + 1024) = Hh.u;
        *(uint32_t*)(ob + 2048) = Ll.u;
        __syncwarp();
    }
}

// ================= launcher =================
extern "C" void kernel_launch(void* const* d_in, const int* in_sizes, int n_in,
                              void* d_out, int out_size)
{
    const float* x  = (const float*)d_in[0];
    const float* Wq = (const float*)d_in[1];
    const float* bq = (const float*)d_in[2];
    const float* Wk = (const float*)d_in[3];
    const float* bk = (const float*)d_in[4];
    const float* Wv = (const float*)d_in[5];
    const float* bv = (const float*)d_in[6];
    const float* Wo = (const float*)d_in[7];
    const float* bo = (const float*)d_in[8];
    float* out = (float*)d_out;

    __nv_bfloat16 *x2, *attn2, *w2;
    float *q, *k, *v;
    cudaGetSymbolAddress((void**)&x2,    g_x2);
    cudaGetSymbolAddress((void**)&attn2, g_attn2);
    cudaGetSymbolAddress((void**)&w2,    g_w2);
    cudaGetSymbolAddress((void**)&q,     g_q);
    cudaGetSymbolAddress((void**)&k,     g_k);
    cudaGetSymbolAddress((void**)&v,     g_v);
    __nv_bfloat16* w2q = w2;
    __nv_bfloat16* w2k = w2 + (size_t)1 * E_ * KTOT;
    __nv_bfloat16* w2v = w2 + (size_t)2 * E_ * KTOT;
    __nv_bfloat16* w2o = w2 + (size_t)3 * E_ * KTOT;

    cudaFuncSetAttribute(gemm_mma<0>, cudaFuncAttributeMaxDynamicSharedMemorySize, GEMM_DSMEM);
    cudaFuncSetAttribute(gemm_mma<1>, cudaFuncAttributeMaxDynamicSharedMemorySize, GEMM_DSMEM);

    // split conversions
    split_kernel<1><<<M_ * (E_/4) / 256, 256>>>(x, x2, M_);
    split_kernel<0><<<E_ * (E_/4) / 256, 256>>>(Wq, w2q, E_);
    split_kernel<0><<<E_ * (E_/4) / 256, 256>>>(Wk, w2k, E_);
    split_kernel<0><<<E_ * (E_/4) / 256, 256>>>(Wv, w2v, E_);
    split_kernel<0><<<E_ * (E_/4) / 256, 256>>>(Wo, w2o, E_);

    dim3 gg(E_ / GBN, M_ / GBM);   // (8, 128)
    gemm_mma<1><<<gg, 256, GEMM_DSMEM>>>(x2, w2q, bq, q);
    gemm_mma<1><<<gg, 256, GEMM_DSMEM>>>(x2, w2k, bk, k);
    gemm_mma<0><<<gg, 256, GEMM_DSMEM>>>(x2, w2v, bv, v);

    kv_partial<<<dim3(BH_, NCHUNK), 256>>>(k, v);
    kv_reduce<<<BH_, 256>>>();
    attn_kernel<<<dim3(32, BH_), 256>>>(q);

    gemm_mma<0><<<gg, 256, GEMM_DSMEM>>>(attn2, w2o, bo, out);
}